// round 7
// baseline (speedup 1.0000x reference)
#include <cuda_runtime.h>

#define NN 16000
#define KNN 16
#define FIN 32
#define HID 64
#define G 64
#define NCELL (G * G)
#define CAP 32            // max points per cell (lambda ~3.9)

// ---------------- scratch (device globals; no allocation allowed) ----------
__device__ float4 g_pts[NN];              // {x, y, x^2+y^2, id-bits}
__device__ float4 g_binpts[NCELL * CAP];  // packed candidates per cell
__device__ int    g_bcnt[NCELL];          // per-cell fill counts
__device__ int    g_knn[NN * KNN];        // neighbor (src) indices (sorted)
__device__ float  g_d  [NN * KNN];        // edge distances
__device__ float  g_ew [NN * KNN];        // normalized inverted distances
__device__ float  g_dis[NN];              // deg^{-1/2}
__device__ unsigned g_minmax[2];          // [0]=min bits, [1]=max bits (d>=0)
__device__ unsigned g_bbox[4];            // ordered-uint minx,maxx,miny,maxy
__device__ float  g_bufA[NN * HID];       // x@W1
__device__ float  g_bufB[NN * HID];       // h1@W2

// ordered-uint map: monotone with float order (handles negatives)
__device__ __forceinline__ unsigned enc_ord(float f) {
    unsigned b = __float_as_uint(f);
    return (b & 0x80000000u) ? ~b : (b | 0x80000000u);
}
__device__ __forceinline__ float dec_ord(unsigned u) {
    return (u & 0x80000000u) ? __uint_as_float(u & 0x7FFFFFFFu)
                             : __uint_as_float(~u);
}

struct Grid { float minx, miny, invsx, invsy, smin; };
__device__ __forceinline__ Grid load_grid() {
    Grid g;
    g.minx = dec_ord(g_bbox[0]);
    float maxx = dec_ord(g_bbox[1]);
    g.miny = dec_ord(g_bbox[2]);
    float maxy = dec_ord(g_bbox[3]);
    float wx = fmaxf(maxx - g.minx, 1e-20f);
    float wy = fmaxf(maxy - g.miny, 1e-20f);
    g.invsx = (float)G / wx;
    g.invsy = (float)G / wy;
    g.smin  = fminf(wx, wy) / (float)G;
    return g;
}
__device__ __forceinline__ int cell_x(const Grid& g, float x) {
    int c = (int)((x - g.minx) * g.invsx);
    return min(max(c, 0), G - 1);
}
__device__ __forceinline__ int cell_y(const Grid& g, float y) {
    int c = (int)((y - g.miny) * g.invsy);
    return min(max(c, 0), G - 1);
}

// ---------------- K1: init + pack + bbox (block-reduced atomics) ------------
__global__ void prep_kernel(const float* __restrict__ c) {
    __shared__ unsigned red[4][8];        // [stat][warp]
    int i = blockIdx.x * 256 + threadIdx.x;
    if (i < NCELL) g_bcnt[i] = 0;
    if (i == 0) { g_minmax[0] = 0x7F800000u; g_minmax[1] = 0u;
                  g_bbox[0] = 0xFFFFFFFFu; g_bbox[1] = 0u;
                  g_bbox[2] = 0xFFFFFFFFu; g_bbox[3] = 0u; }
    unsigned exn = 0xFFFFFFFFu, exx = 0u, eyn = 0xFFFFFFFFu, eyx = 0u;
    if (i < NN) {
        float x = c[2 * i], y = c[2 * i + 1];
        float sq = __fadd_rn(__fmul_rn(x, x), __fmul_rn(y, y));
        g_pts[i] = make_float4(x, y, sq, __int_as_float(i));
        unsigned ex = enc_ord(x), ey = enc_ord(y);
        exn = ex; exx = ex; eyn = ey; eyx = ey;
    }
    exn = __reduce_min_sync(0xFFFFFFFFu, exn);
    exx = __reduce_max_sync(0xFFFFFFFFu, exx);
    eyn = __reduce_min_sync(0xFFFFFFFFu, eyn);
    eyx = __reduce_max_sync(0xFFFFFFFFu, eyx);
    int w = threadIdx.x >> 5;
    if ((threadIdx.x & 31) == 0) {
        red[0][w] = exn; red[1][w] = exx; red[2][w] = eyn; red[3][w] = eyx;
    }
    __syncthreads();
    if (threadIdx.x < 4) {
        unsigned v = red[threadIdx.x][0];
        bool ismin = (threadIdx.x & 1) == 0;
#pragma unroll
        for (int k = 1; k < 8; k++)
            v = ismin ? min(v, red[threadIdx.x][k]) : max(v, red[threadIdx.x][k]);
        if (ismin) atomicMin(&g_bbox[threadIdx.x], v);
        else       atomicMax(&g_bbox[threadIdx.x], v);
    }
}

// ---------------- K2: bin fill -----------------------------------------------
__global__ void fill_kernel() {
    int i = blockIdx.x * 256 + threadIdx.x;
    if (i >= NN) return;
    Grid g = load_grid();
    float4 p = g_pts[i];
    int cell = cell_y(g, p.y) * G + cell_x(g, p.x);
    int slot = atomicAdd(&g_bcnt[cell], 1);
    if (slot < CAP) g_binpts[cell * CAP + slot] = p;
}

// ---------------- K3: x@W1 ---------------------------------------------------
__global__ void mm1_kernel(const float* __restrict__ x,
                           const float* __restrict__ W1) {
    __shared__ float sw[FIN * 64];
    int tid = threadIdx.x;
    for (int i = tid; i < FIN * 64; i += 256) sw[i] = W1[i];
    __syncthreads();
    int n = blockIdx.x * 4 + (tid >> 6);
    int f = tid & 63;
    const float* xr = x + n * FIN;
    float acc = 0.0f;
#pragma unroll
    for (int k = 0; k < FIN; k++) acc = fmaf(xr[k], sw[k * 64 + f], acc);
    g_bufA[n * 64 + f] = acc;
}

// ---------------- K4 (PROFILED SLOT): exact KNN + edge distances ------------
// Queries enumerated as (cell, slot) straight from the bins -> warps cover
// adjacent cells (spatial coherence). min-16 of key=(ordered(d2)<<32|j)
// tracked unsorted via branchless replace-max over DISTINCT sentinels
// (~0ULL - t; real keys have high word <= 0xFF800000, never collide).
// Final static bubble sort -> output == top_k(-d2) with low-idx ties.
#define PHA (NCELL * 8 / 256)             // 128
#define PHB (NCELL * 24 / 256)            // 384
__global__ void knn_edge_kernel() {
    __shared__ unsigned smn, smx;
    if (threadIdx.x == 0) { smn = 0x7F800000u; smx = 0u; }
    __syncthreads();

    int cell, slot;
    if (blockIdx.x < PHA) {
        int t = blockIdx.x * 256 + threadIdx.x;
        cell = t >> 3; slot = t & 7;
    } else {
        int t = (blockIdx.x - PHA) * 256 + threadIdx.x;
        cell = t / 24; slot = 8 + t % 24;
    }
    const int cnt0 = min(g_bcnt[cell], CAP);
    const bool active = slot < cnt0;

    if (active) {
        const Grid g = load_grid();
        const float4 me = g_binpts[cell * CAP + slot];
        const int q = __float_as_int(me.w);
        const int cx = cell & (G - 1);
        const int cy = cell >> 6;

        unsigned long long keys[16];
#pragma unroll
        for (int t = 0; t < 16; t++) keys[t] = ~0ULL - (unsigned long long)t;
        unsigned long long cmax = ~0ULL;

        for (int r = 0; r < G; r++) {
            if (r >= 2) {
                float b = (float)(r - 1) * g.smin;
                float thr = dec_ord((unsigned)(cmax >> 32)); // NaN if sentinel
                if (b * b > thr + 1e-4f) break;              // NaN -> false
            }
            int y0 = cy - r, y1 = cy + r, x0 = cx - r, x1 = cx + r;
            for (int yy = max(y0, 0); yy <= min(y1, G - 1); yy++) {
                bool erow = (yy == y0) || (yy == y1);
                int xstep = (erow || r == 0) ? 1 : 2 * r;
                for (int xx = x0; xx <= x1; xx += xstep) {
                    if (xx < 0 || xx >= G) continue;
                    int cc = yy * G + xx;
                    int cnt = min(g_bcnt[cc], CAP);
                    const float4* bp = &g_binpts[cc * CAP];
                    for (int p = 0; p < cnt; p++) {
                        float4 pt = bp[p];
                        int j = __float_as_int(pt.w);
                        float dot = __fmaf_rn(me.y, pt.y,
                                              __fmul_rn(me.x, pt.x));
                        float d2  = __fsub_rn(__fadd_rn(me.z, pt.z),
                                              __fmul_rn(2.0f, dot));
                        unsigned long long key =
                            ((unsigned long long)enc_ord(d2) << 32) |
                            (unsigned)j;
                        if (j != q && key < cmax) {
                            unsigned long long nm = 0ULL;
#pragma unroll
                            for (int t = 0; t < 16; t++) {
                                if (keys[t] == cmax) keys[t] = key;
                                nm = max(nm, keys[t]);
                            }
                            cmax = nm;
                        }
                    }
                }
            }
        }

        // sort 16 keys ascending (static bubble network, registers only)
#pragma unroll
        for (int i = 0; i < 15; i++)
#pragma unroll
            for (int t = 0; t < 15 - i; t++)
                if (keys[t] > keys[t + 1]) {
                    unsigned long long tmp = keys[t];
                    keys[t] = keys[t + 1];
                    keys[t + 1] = tmp;
                }

        // edge epilogue: distances + local minmax
        unsigned lmn = 0x7F800000u, lmx = 0u;
#pragma unroll
        for (int t = 0; t < 16; t++) {
            int j = (int)(keys[t] & 0xFFFFFFFFULL);
            g_knn[q * KNN + t] = j;
            float4 nb = g_pts[j];
            float dx = __fsub_rn(me.x, nb.x);
            float dy = __fsub_rn(me.y, nb.y);
            float d  = __fsqrt_rn(__fadd_rn(__fmul_rn(dx, dx),
                                            __fmul_rn(dy, dy)));
            g_d[q * KNN + t] = d;
            unsigned b = __float_as_uint(d);    // d>=0 -> order-preserving
            lmn = min(lmn, b);
            lmx = max(lmx, b);
        }
        atomicMin(&smn, lmn);
        atomicMax(&smx, lmx);
    }
    __syncthreads();
    if (threadIdx.x == 0) {
        atomicMin(&g_minmax[0], smn);
        atomicMax(&g_minmax[1], smx);
    }
}

// ---------------- K5: edge weights + deg^{-1/2} (1 thread / edge) -----------
__global__ void deg_kernel() {
    int e = blockIdx.x * 256 + threadIdx.x;     // coalesced over edges
    float mx  = __uint_as_float(g_minmax[1]);
    float rng = __fsub_rn(mx, __uint_as_float(g_minmax[0]));
    float ew  = __fdiv_rn(__fsub_rn(mx, g_d[e]), rng);
    g_ew[e] = ew;
    float s = ew;
#pragma unroll
    for (int off = 8; off > 0; off >>= 1)
        s += __shfl_down_sync(0xFFFFFFFFu, s, off, 16);
    if ((threadIdx.x & 15) == 0)
        g_dis[e >> 4] = rsqrtf(__fadd_rn(1.0f, s));   // +1 self-loop
}

// ---------------- K6: agg1 + relu + h1@W2 (row-fused) -----------------------
#define NPB 8
__global__ void agg_mm2_kernel(const float* __restrict__ b1,
                               const float* __restrict__ W2) {
    __shared__ float sw[HID * 64];
    __shared__ float sh1[NPB][64];
    int tid = threadIdx.y * 64 + threadIdx.x;
    for (int i = tid; i < HID * 64; i += 64 * NPB) sw[i] = W2[i];
    int n = blockIdx.x * NPB + threadIdx.y;
    int f = threadIdx.x;
    float disn = g_dis[n];
    float acc = __fmul_rn(__fmul_rn(disn, disn), g_bufA[n * 64 + f]);
#pragma unroll
    for (int k = 0; k < KNN; k++) {
        int s = g_knn[n * KNN + k];
        float coef = __fmul_rn(__fmul_rn(g_dis[s], g_ew[n * KNN + k]), disn);
        acc = fmaf(coef, g_bufA[s * 64 + f], acc);
    }
    sh1[threadIdx.y][f] = fmaxf(__fadd_rn(acc, b1[f]), 0.0f);
    __syncthreads();
    float acc2 = 0.0f;
#pragma unroll
    for (int k = 0; k < HID; k++)
        acc2 = fmaf(sh1[threadIdx.y][k], sw[k * 64 + f], acc2);
    g_bufB[n * 64 + f] = acc2;
}

// ---------------- K7: agg2 + relu + FC head ---------------------------------
__global__ void final_kernel(const float* __restrict__ b2,
                             const float* __restrict__ wfc,
                             const float* __restrict__ bfc,
                             float* __restrict__ y) {
    __shared__ float red[NPB][64];
    int n = blockIdx.x * NPB + threadIdx.y;
    int f = threadIdx.x;
    float disn = g_dis[n];
    float acc = __fmul_rn(__fmul_rn(disn, disn), g_bufB[n * 64 + f]);
#pragma unroll
    for (int k = 0; k < KNN; k++) {
        int s = g_knn[n * KNN + k];
        float coef = __fmul_rn(__fmul_rn(g_dis[s], g_ew[n * KNN + k]), disn);
        acc = fmaf(coef, g_bufB[s * 64 + f], acc);
    }
    float h2 = fmaxf(__fadd_rn(acc, b2[f]), 0.0f);
    red[threadIdx.y][f] = h2 * wfc[f];
    __syncthreads();
#pragma unroll
    for (int off = 32; off > 0; off >>= 1) {
        if (f < off) red[threadIdx.y][f] += red[threadIdx.y][f + off];
        __syncthreads();
    }
    if (f == 0) y[n] = red[threadIdx.y][0] + bfc[0];
}

// ---------------- launch -----------------------------------------------------
extern "C" void kernel_launch(void* const* d_in, const int* in_sizes, int n_in,
                              void* d_out, int out_size) {
    const float* x   = (const float*)d_in[0];
    const float* c   = (const float*)d_in[1];
    const float* W1  = (const float*)d_in[2];
    const float* b1  = (const float*)d_in[3];
    const float* W2  = (const float*)d_in[4];
    const float* b2  = (const float*)d_in[5];
    const float* Wfc = (const float*)d_in[6];
    const float* bfc = (const float*)d_in[7];
    float* y = (float*)d_out;

    prep_kernel<<<63, 256>>>(c);          // launch 0
    fill_kernel<<<63, 256>>>();           // launch 1
    mm1_kernel<<<NN / 4, 256>>>(x, W1);   // launch 2
    knn_edge_kernel<<<PHA + PHB, 256>>>(); // launch 3  <- profiled slot
    deg_kernel<<<NN * KNN / 256, 256>>>();
    dim3 blk(64, NPB);
    agg_mm2_kernel<<<NN / NPB, blk>>>(b1, W2);
    final_kernel<<<NN / NPB, blk>>>(b2, Wfc, bfc, y);
}